// round 2
// baseline (speedup 1.0000x reference)
#include <cuda_runtime.h>
#include <cuda_bf16.h>

// MX quantize-dequantize: block size 32, E8M0 shared scale, E4M3 elements.
// Layout: 4 threads per 32-element block; each thread owns 8 contiguous
// elements (two float4 loads/stores). amax reduced across the 4 lanes with
// two shfl.xor. All scale/quantum arithmetic uses exact power-of-two
// bit-constructed floats (no division, no log2f/exp2f).

__device__ __forceinline__ float mx_qdq_elem(float v, float inv_scale, float scale) {
    unsigned sbit = __float_as_uint(v) & 0x80000000u;
    // x / scale, exact (power-of-two multiply); magnitude path only
    float mag = fabsf(v) * inv_scale;
    // E4M3 saturation
    mag = fminf(mag, 448.0f);
    // e = max(floor(log2(max(mag, 2^-6))), -6); exponent-field extract is exact
    float safe = fmaxf(mag, 0.015625f); // 2^-6
    int e = (int)(__float_as_uint(safe) >> 23) - 127;
    // quantum = 2^(e-3), inv_quantum = 2^(3-e); both normal fp32 (e in [-6, 8])
    float quantum = __uint_as_float((unsigned)((e - 3) + 127) << 23);
    float invq    = __uint_as_float((unsigned)((3 - e) + 127) << 23);
    // round-half-to-even (matches jnp.round), then dequantize (exact pow2 mults)
    float q = rintf(mag * invq) * quantum * scale;
    return __uint_as_float(__float_as_uint(q) | sbit);
}

__global__ void __launch_bounds__(256)
mx_qdq_kernel(const float4* __restrict__ x, float4* __restrict__ y, int nvec) {
    int t  = blockIdx.x * blockDim.x + threadIdx.x;
    int i0 = t * 2;
    if (i0 + 1 >= nvec) return;

    float4 a = x[i0];
    float4 b = x[i0 + 1];

    // per-thread amax over 8 elements
    float m = fmaxf(fmaxf(fmaxf(fabsf(a.x), fabsf(a.y)), fmaxf(fabsf(a.z), fabsf(a.w))),
                    fmaxf(fmaxf(fabsf(b.x), fabsf(b.y)), fmaxf(fabsf(b.z), fabsf(b.w))));

    // reduce amax across the 4 lanes sharing this 32-element block
    m = fmaxf(m, __shfl_xor_sync(0xffffffffu, m, 1));
    m = fmaxf(m, __shfl_xor_sync(0xffffffffu, m, 2));

    // shared_exp = clip(floor(log2(amax)) - 8, -127, 127); exact via exponent field.
    // (amax==0 -> all elements 0 -> scale value irrelevant. Lower clamp at -126
    //  keeps the bit-constructed scale normal; the -127 case is unreachable for
    //  any block whose amax >= 2^-118.)
    int eamax = (int)(__float_as_uint(m) >> 23) - 127;
    int se = eamax - 8;
    se = max(se, -126);
    float scale     = __uint_as_float((unsigned)(se + 127) << 23);
    float inv_scale = __uint_as_float((unsigned)(127 - se) << 23);

    float4 oa, ob;
    oa.x = mx_qdq_elem(a.x, inv_scale, scale);
    oa.y = mx_qdq_elem(a.y, inv_scale, scale);
    oa.z = mx_qdq_elem(a.z, inv_scale, scale);
    oa.w = mx_qdq_elem(a.w, inv_scale, scale);
    ob.x = mx_qdq_elem(b.x, inv_scale, scale);
    ob.y = mx_qdq_elem(b.y, inv_scale, scale);
    ob.z = mx_qdq_elem(b.z, inv_scale, scale);
    ob.w = mx_qdq_elem(b.w, inv_scale, scale);

    y[i0]     = oa;
    y[i0 + 1] = ob;
}

extern "C" void kernel_launch(void* const* d_in, const int* in_sizes, int n_in,
                              void* d_out, int out_size) {
    const float* x = (const float*)d_in[0];
    float*       y = (float*)d_out;
    int n    = in_sizes[0];      // 4096*8192 = 33,554,432 (divisible by 32)
    int nvec = n / 4;            // float4 count
    int nthreads = nvec / 2;     // 8 elements per thread
    int block = 256;
    int grid  = (nthreads + block - 1) / block;
    mx_qdq_kernel<<<grid, block>>>((const float4*)x, (float4*)y, nvec);
}